// round 1
// baseline (speedup 1.0000x reference)
#include <cuda_runtime.h>
#include <math.h>

// ---------------------------------------------------------------------------
// QuanvolutionFilter: 4-qubit circuit on 2x2 patches.
// ev_w(theta) = q01^T C_w q23, where q = (1,cos,sin) x (1,cos,sin) per wire
// pair, and C_w (9x9) is precomputed from params once per launch.
// ---------------------------------------------------------------------------

#define N_WIRES 4
#define N_LAYERS 2

// C coefficients, rows padded to 12 floats for float4 loads (pad = 0).
__device__ float g_C[4][9][12];

struct C2 { float r, i; };
__device__ __forceinline__ C2 cmul(C2 a, C2 b) { return {a.r*b.r - a.i*b.i, a.r*b.i + a.i*b.r}; }

// ---------------------------------------------------------------------------
// Setup kernel: 1 block, 256 threads.
// Phase 1: 16 threads each evolve one basis column of U through the circuit.
// Phase 2: A_w[j][k] = Re( sum_i conj(U[i][j]) * sign(i,w) * U[i][k] ).
// Phase 3: project A_w (16x16) onto the 81-monomial basis -> g_C.
// ---------------------------------------------------------------------------
__global__ void quanv_setup_kernel(const float* __restrict__ params) {
    __shared__ float2 U[16][16];      // U[i][j] = <i| U_circuit |j>
    __shared__ float  A[4][16][16];   // real symmetric observables
    const int tid = threadIdx.x;

    if (tid < 16) {
        C2 col[16];
        #pragma unroll
        for (int i = 0; i < 16; i++) col[i] = {(i == tid) ? 1.0f : 0.0f, 0.0f};

        #pragma unroll
        for (int l = 0; l < N_LAYERS; l++) {
            #pragma unroll
            for (int w = 0; w < N_WIRES; w++) {
                const int mask = 1 << (3 - w);       // wire 0 = MSB of state index
                const float* pw = params + (l * N_WIRES + w) * 3;
                // RX(t): [[c, -is], [-is, c]]
                {
                    float t = pw[0], c = cosf(0.5f * t), s = sinf(0.5f * t);
                    #pragma unroll
                    for (int i = 0; i < 16; i++) if (!(i & mask)) {
                        int i1 = i | mask;
                        C2 a = col[i], b = col[i1];
                        col[i]  = {c*a.r + s*b.i, c*a.i - s*b.r};   // c*a + (-is)*b
                        col[i1] = {s*a.i + c*b.r, -s*a.r + c*b.i};  // (-is)*a + c*b
                    }
                }
                // RY(t): [[c, -s], [s, c]]
                {
                    float t = pw[1], c = cosf(0.5f * t), s = sinf(0.5f * t);
                    #pragma unroll
                    for (int i = 0; i < 16; i++) if (!(i & mask)) {
                        int i1 = i | mask;
                        C2 a = col[i], b = col[i1];
                        col[i]  = {c*a.r - s*b.r, c*a.i - s*b.i};
                        col[i1] = {s*a.r + c*b.r, s*a.i + c*b.i};
                    }
                }
                // RZ(t): diag(e^{-it/2}, e^{+it/2})
                {
                    float t = pw[2], c = cosf(0.5f * t), s = sinf(0.5f * t);
                    C2 em = {c, -s}, ep = {c, s};
                    #pragma unroll
                    for (int i = 0; i < 16; i++)
                        col[i] = (i & mask) ? cmul(ep, col[i]) : cmul(em, col[i]);
                }
            }
            // CNOT ring: (0,1), (1,2), (2,3), (3,0). Swap target pair where ctrl=1.
            const int cw[4] = {0, 1, 2, 3};
            const int tw[4] = {1, 2, 3, 0};
            #pragma unroll
            for (int k = 0; k < 4; k++) {
                const int cmask = 1 << (3 - cw[k]);
                const int tmask = 1 << (3 - tw[k]);
                #pragma unroll
                for (int i = 0; i < 16; i++) if ((i & cmask) && !(i & tmask)) {
                    int i1 = i | tmask;
                    C2 tmp = col[i]; col[i] = col[i1]; col[i1] = tmp;
                }
            }
        }
        #pragma unroll
        for (int i = 0; i < 16; i++) U[i][tid] = make_float2(col[i].r, col[i].i);
    }
    __syncthreads();

    // Phase 2: A_w = Re(U^H Z_w U)
    for (int idx = tid; idx < 4 * 16 * 16; idx += blockDim.x) {
        int w = idx >> 8, j = (idx >> 4) & 15, k = idx & 15;
        float sum = 0.0f;
        #pragma unroll
        for (int i = 0; i < 16; i++) {
            float sgn = ((i >> (3 - w)) & 1) ? -1.0f : 1.0f;
            float2 uj = U[i][j], uk = U[i][k];
            sum += sgn * (uj.x * uk.x + uj.y * uk.y);
        }
        A[w][j][k] = sum;
    }
    __syncthreads();

    // Phase 3: per wire, (j,k) basis -> (1, cos, sin) basis.
    //   t=0: (0,0)->+1/2, (1,1)->+1/2
    //   t=1: (0,0)->+1/2, (1,1)->-1/2
    //   t=2: (0,1)->+1/2, (1,0)->+1/2
    // Each C entry is a signed sum of 16 A entries, scaled by 1/16.
    for (int idx = tid; idx < 4 * 9 * 12; idx += blockDim.x) {
        int w = idx / 108;
        int rem = idx % 108;
        int a = rem / 12, bi = rem % 12;
        float val = 0.0f;
        if (bi < 9) {
            int t[4] = { a / 3, a % 3, bi / 3, bi % 3 };
            float sum = 0.0f;
            for (int cc = 0; cc < 16; cc++) {
                int j = 0, k = 0;
                float sgn = 1.0f;
                #pragma unroll
                for (int u = 0; u < 4; u++) {
                    int sel = (cc >> u) & 1;
                    int ju, ku;
                    if (t[u] == 0)      { ju = sel; ku = sel; }
                    else if (t[u] == 1) { ju = sel; ku = sel; if (sel) sgn = -sgn; }
                    else                { ju = sel; ku = 1 - sel; }
                    j |= ju << (3 - u);
                    k |= ku << (3 - u);
                }
                sum += sgn * A[w][j][k];
            }
            val = sum * (1.0f / 16.0f);
        }
        g_C[w][a][bi] = val;
    }
}

// ---------------------------------------------------------------------------
// Main kernel: one thread per patch (200704 total = 784 blocks x 256).
// ---------------------------------------------------------------------------
__global__ void __launch_bounds__(256) quanv_main_kernel(
    const float* __restrict__ x, float* __restrict__ out) {
    __shared__ __align__(16) float Cs[4][9][12];
    {
        const float* src = &g_C[0][0][0];
        float* dst = &Cs[0][0][0];
        for (int i = threadIdx.x; i < 4 * 9 * 12; i += 256) dst[i] = src[i];
    }
    __syncthreads();

    const int p = blockIdx.x * 256 + threadIdx.x;   // global patch id, exact grid
    const int b = p / 196;
    const int pp = p - b * 196;
    const int r = pp / 14;
    const int c = pp - r * 14;

    // patch pixels: x[b, 2r, 2c], x[b, 2r, 2c+1], x[b, 2r+1, 2c], x[b, 2r+1, 2c+1]
    const float2* x2 = (const float2*)x;
    const int base = b * 392 + r * 28 + c;          // float2 index of (2r, 2c)
    const float2 f01 = __ldg(&x2[base]);
    const float2 f23 = __ldg(&x2[base + 14]);

    float s0, c0, s1, c1, s2, c2, s3, c3;
    __sincosf(f01.x, &s0, &c0);
    __sincosf(f01.y, &s1, &c1);
    __sincosf(f23.x, &s2, &c2);
    __sincosf(f23.y, &s3, &c3);

    // q[a = t0*3+t1] = g0(t0)*g1(t1), g = (1, cos, sin)
    float q01[9] = {1.0f, c1, s1, c0, c0*c1, c0*s1, s0, s0*c1, s0*s1};
    float q23[9] = {1.0f, c3, s3, c2, c2*c3, c2*s3, s2, s2*c3, s2*s3};

    float evv[4];
    #pragma unroll
    for (int w = 0; w < 4; w++) {
        float acc = 0.0f;
        #pragma unroll
        for (int a = 0; a < 9; a++) {
            const float4* row = (const float4*)(&Cs[w][a][0]);
            float4 v0 = row[0];
            float4 v1 = row[1];
            float s = v0.x * q23[0];
            s = fmaf(v0.y, q23[1], s);
            s = fmaf(v0.z, q23[2], s);
            s = fmaf(v0.w, q23[3], s);
            s = fmaf(v1.x, q23[4], s);
            s = fmaf(v1.y, q23[5], s);
            s = fmaf(v1.z, q23[6], s);
            s = fmaf(v1.w, q23[7], s);
            s = fmaf(Cs[w][a][8], q23[8], s);
            acc = fmaf(q01[a], s, acc);
        }
        evv[w] = acc;
    }

    // out[b, pp*4 + w] == out[p*4 + w] : one float4 per patch
    ((float4*)out)[p] = make_float4(evv[0], evv[1], evv[2], evv[3]);
}

// ---------------------------------------------------------------------------
extern "C" void kernel_launch(void* const* d_in, const int* in_sizes, int n_in,
                              void* d_out, int out_size) {
    const float* x = (const float*)d_in[0];
    const float* params = (const float*)d_in[1];
    if (n_in >= 2 && in_sizes[0] == N_LAYERS * N_WIRES * 3) {
        // defensive: inputs arrived as (params, x)
        const float* tmp = x; x = params; params = tmp;
    }
    quanv_setup_kernel<<<1, 256>>>(params);
    quanv_main_kernel<<<784, 256>>>(x, (float*)d_out);
}

// round 2
// speedup vs baseline: 1.7826x; 1.7826x over previous
#include <cuda_runtime.h>
#include <math.h>

// ---------------------------------------------------------------------------
// QuanvolutionFilter: 4-qubit circuit on 2x2 patches.
// ev_w(theta) = q01^T C_w q23 with q = (1,cos,sin)x(1,cos,sin) per wire pair.
// C_w (9x9) precomputed from params by a warp-parallel setup kernel; the main
// kernel evaluates the bilinear form with packed f32x2 FFMAs, 2 patches/thread.
// ---------------------------------------------------------------------------

#define N_WIRES 4
#define N_LAYERS 2

// Interleaved coefficients: g_Cp[a*9+b] = (C0, C1, C2, C3) for wires 0..3.
__device__ __align__(16) float4 g_Cp[81];

// ---- f32x2 packed helpers (sm_10x) ----------------------------------------
__device__ __forceinline__ unsigned long long pack2(float lo, float hi) {
    unsigned long long r;
    asm("mov.b64 %0, {%1, %2};" : "=l"(r) : "f"(lo), "f"(hi));
    return r;
}
__device__ __forceinline__ void unpack2(unsigned long long v, float& lo, float& hi) {
    asm("mov.b64 {%0, %1}, %2;" : "=f"(lo), "=f"(hi) : "l"(v));
}
__device__ __forceinline__ unsigned long long ffma2(
    unsigned long long a, unsigned long long b, unsigned long long c) {
    unsigned long long d;
    asm("fma.rn.f32x2 %0, %1, %2, %3;" : "=l"(d) : "l"(a), "l"(b), "l"(c));
    return d;
}

// ---------------------------------------------------------------------------
// Setup kernel: 1 block, 256 threads.
// Phase 1 (warp-parallel): lane holds one complex amplitude of one basis
//   column; gates applied via shfl_xor. warp k owns columns 2k, 2k+1.
// Phase 2: A_w = Re(U^H Z_w U)  (4 x 16 x 16)
// Phase 3: project A_w onto the 81-monomial (1,cos,sin)^x4 basis -> g_Cp.
// ---------------------------------------------------------------------------
__global__ void quanv_setup_kernel(const float* __restrict__ params) {
    __shared__ float2 U[16][16];      // U[i][j]
    __shared__ float  A[4][16][16];

    const int tid  = threadIdx.x;
    const int lane = tid & 31;
    const int warp = tid >> 5;
    const int i    = lane & 15;                 // amplitude (state) index
    const int j    = (warp << 1) | (lane >> 4); // basis column

    // |psi> = |j>
    float ar = (i == j) ? 1.0f : 0.0f;
    float ai = 0.0f;

    #pragma unroll
    for (int l = 0; l < N_LAYERS; l++) {
        #pragma unroll
        for (int w = 0; w < N_WIRES; w++) {
            const int m   = 8 >> w;             // wire 0 = MSB
            const bool bit = (i & m) != 0;
            const float* pw = params + (l * N_WIRES + w) * 3;
            float s, c, pr, pi, nr, ni;
            // RX
            __sincosf(0.5f * pw[0], &s, &c);
            pr = __shfl_xor_sync(0xFFFFFFFFu, ar, m);
            pi = __shfl_xor_sync(0xFFFFFFFFu, ai, m);
            nr = c * ar + s * pi;  ni = c * ai - s * pr;  ar = nr; ai = ni;
            // RY
            __sincosf(0.5f * pw[1], &s, &c);
            pr = __shfl_xor_sync(0xFFFFFFFFu, ar, m);
            pi = __shfl_xor_sync(0xFFFFFFFFu, ai, m);
            {
                float sg = bit ? s : -s;
                nr = c * ar + sg * pr;  ni = c * ai + sg * pi;  ar = nr; ai = ni;
            }
            // RZ: diag(e^{-it/2}, e^{+it/2})
            __sincosf(0.5f * pw[2], &s, &c);
            {
                float z = bit ? s : -s;
                nr = c * ar - z * ai;  ni = c * ai + z * ar;  ar = nr; ai = ni;
            }
        }
        // CNOT ring (ctrl k -> tgt (k+1)%4): swap target pair where ctrl=1
        #pragma unroll
        for (int k = 0; k < 4; k++) {
            const int cm = 8 >> k;
            const int tm = 8 >> ((k + 1) & 3);
            float pr = __shfl_xor_sync(0xFFFFFFFFu, ar, tm);
            float pi = __shfl_xor_sync(0xFFFFFFFFu, ai, tm);
            if (i & cm) { ar = pr; ai = pi; }
        }
    }
    U[i][j] = make_float2(ar, ai);
    __syncthreads();

    // Phase 2: A_w[j][k] = sum_i sign(i,w) * Re(conj(U[i][j]) U[i][k])
    for (int idx = tid; idx < 4 * 16 * 16; idx += 256) {
        int w = idx >> 8, jj = (idx >> 4) & 15, kk = idx & 15;
        float sum = 0.0f;
        #pragma unroll
        for (int ii = 0; ii < 16; ii++) {
            float sgn = ((ii >> (3 - w)) & 1) ? -1.0f : 1.0f;
            float2 uj = U[ii][jj], uk = U[ii][kk];
            sum += sgn * (uj.x * uk.x + uj.y * uk.y);
        }
        A[w][jj][kk] = sum;
    }
    __syncthreads();

    // Phase 3: (j,k) -> (1,cos,sin) basis per wire.
    //   t=0 (1):   +A00 +A11 ; t=1 (cos): +A00 -A11 ; t=2 (sin): +A01 +A10
    // each with factor 1/2 per wire -> global 1/16.
    for (int idx = tid; idx < 324; idx += 256) {
        const int w = idx & 3;
        const int e = idx >> 2;
        const int a = e / 9, b = e % 9;
        const int t0 = a / 3, t1 = a % 3, t2 = b / 3, t3 = b % 3;
        float sum = 0.0f;
        #pragma unroll
        for (int cc = 0; cc < 16; cc++) {
            int jj = 0, kk = 0, neg = 0;
            { int sel = cc & 1;        jj |= sel << 3; kk |= ((t0 == 2) ? (sel ^ 1) : sel) << 3; neg ^= (t0 == 1) & sel; }
            { int sel = (cc >> 1) & 1; jj |= sel << 2; kk |= ((t1 == 2) ? (sel ^ 1) : sel) << 2; neg ^= (t1 == 1) & sel; }
            { int sel = (cc >> 2) & 1; jj |= sel << 1; kk |= ((t2 == 2) ? (sel ^ 1) : sel) << 1; neg ^= (t2 == 1) & sel; }
            { int sel = (cc >> 3) & 1; jj |= sel;      kk |= ((t3 == 2) ? (sel ^ 1) : sel);      neg ^= (t3 == 1) & sel; }
            float av = A[w][jj][kk];
            sum += neg ? -av : av;
        }
        ((float*)g_Cp)[e * 4 + w] = sum * (1.0f / 16.0f);
    }
}

// ---------------------------------------------------------------------------
// Main kernel: 2 patches per thread, packed f32x2 math.
// 200704 patches -> 392 blocks x 256 threads.
// ---------------------------------------------------------------------------
__device__ __forceinline__ void make_q(
    float2 f01, float2 f23, float* q01, unsigned long long* qq23) {
    float s0, c0, s1, c1, s2, c2, s3, c3;
    __sincosf(f01.x, &s0, &c0);
    __sincosf(f01.y, &s1, &c1);
    __sincosf(f23.x, &s2, &c2);
    __sincosf(f23.y, &s3, &c3);
    q01[0] = 1.0f;    q01[1] = c1;      q01[2] = s1;
    q01[3] = c0;      q01[4] = c0 * c1; q01[5] = c0 * s1;
    q01[6] = s0;      q01[7] = s0 * c1; q01[8] = s0 * s1;
    float q23[9] = {1.0f, c3, s3, c2, c2 * c3, c2 * s3, s2, s2 * c3, s2 * s3};
    #pragma unroll
    for (int b = 0; b < 9; b++) qq23[b] = pack2(q23[b], q23[b]);
}

__global__ void __launch_bounds__(256, 2) quanv_main_kernel(
    const float* __restrict__ x, float* __restrict__ out) {
    __shared__ __align__(16) ulonglong2 Cs[81];
    for (int i = threadIdx.x; i < 81; i += 256)
        Cs[i] = ((const ulonglong2*)g_Cp)[i];
    __syncthreads();

    const int tid = threadIdx.x;
    const int p0  = blockIdx.x * 512 + tid;
    const int p1  = p0 + 256;

    const float2* x2 = (const float2*)x;

    // patch A
    float q01A[9]; unsigned long long qqA[9];
    {
        int b = p0 / 196, pp = p0 - b * 196;
        int r = pp / 14,  c = pp - r * 14;
        int base = b * 392 + r * 28 + c;
        make_q(__ldg(&x2[base]), __ldg(&x2[base + 14]), q01A, qqA);
    }
    // patch B
    float q01B[9]; unsigned long long qqB[9];
    {
        int b = p1 / 196, pp = p1 - b * 196;
        int r = pp / 14,  c = pp - r * 14;
        int base = b * 392 + r * 28 + c;
        make_q(__ldg(&x2[base]), __ldg(&x2[base + 14]), q01B, qqB);
    }

    unsigned long long aA01 = 0, aA23 = 0, aB01 = 0, aB23 = 0;
    #pragma unroll
    for (int a = 0; a < 9; a++) {
        unsigned long long sA01 = 0, sA23 = 0, sB01 = 0, sB23 = 0;
        #pragma unroll
        for (int b = 0; b < 9; b++) {
            ulonglong2 v = Cs[a * 9 + b];   // (C0,C1) | (C2,C3), broadcast LDS.128
            sA01 = ffma2(v.x, qqA[b], sA01);
            sA23 = ffma2(v.y, qqA[b], sA23);
            sB01 = ffma2(v.x, qqB[b], sB01);
            sB23 = ffma2(v.y, qqB[b], sB23);
        }
        unsigned long long pA = pack2(q01A[a], q01A[a]);
        unsigned long long pB = pack2(q01B[a], q01B[a]);
        aA01 = ffma2(sA01, pA, aA01);
        aA23 = ffma2(sA23, pA, aA23);
        aB01 = ffma2(sB01, pB, aB01);
        aB23 = ffma2(sB23, pB, aB23);
    }

    float e0, e1, e2, e3;
    unpack2(aA01, e0, e1); unpack2(aA23, e2, e3);
    ((float4*)out)[p0] = make_float4(e0, e1, e2, e3);
    unpack2(aB01, e0, e1); unpack2(aB23, e2, e3);
    ((float4*)out)[p1] = make_float4(e0, e1, e2, e3);
}

// ---------------------------------------------------------------------------
extern "C" void kernel_launch(void* const* d_in, const int* in_sizes, int n_in,
                              void* d_out, int out_size) {
    const float* x = (const float*)d_in[0];
    const float* params = (const float*)d_in[1];
    if (n_in >= 2 && in_sizes[0] == N_LAYERS * N_WIRES * 3) {
        const float* tmp = x; x = params; params = tmp;  // defensive swap
    }
    quanv_setup_kernel<<<1, 256>>>(params);
    quanv_main_kernel<<<392, 256>>>(x, (float*)d_out);
}